// round 11
// baseline (speedup 1.0000x reference)
#include <cuda_runtime.h>
#include <math.h>

#define V 50000
#define E 5000
#define E4 (E / 4)            // 1250 uint4 per H row
#define ROWB (E * 4)          // 20000 bytes per H row (mult of 16)
#define RPC 50                // rows per CTA in build (V/50 = 1000 CTAs)
#define NBLD (V / RPC)        // 1000
#define CAP 1536              // per-edge list capacity (deg ~ 1001 +- 31)
#define GPART 4               // warps cooperating per edge in gather
#define TAUF 0.5f
#define EPSF 1e-8f

// Scratch (__device__ globals; allocation-free rule)
__device__ __align__(16) float g_P[(size_t)V * 32];   // packed softmax [v][0..15]=ps,[16..31]=pt
__device__ int   g_cnt[E];                            // per-edge nonzero count (= deg_e)
__device__ __align__(16) int g_list[(size_t)E * CAP]; // per-edge vertex lists (unordered)
__device__ float g_Ssum[(size_t)E * 32];              // [e][c] channel sums (atomic-combined)
__device__ float g_Sdeg[E];                           // deg_e (float)
__device__ float g_acc[2];                            // {kl_sum, mask_count}
__device__ int   g_not_int01;                         // mask-dtype detection flags
__device__ int   g_not_f01;

// ---------------------------------------------------------------------------
// TMA bulk 1D + mbarrier helpers
// ---------------------------------------------------------------------------
__device__ __forceinline__ unsigned smem_u32(const void* p) {
    return (unsigned)__cvta_generic_to_shared(p);
}
__device__ __forceinline__ void mbar_init(unsigned addr, unsigned cnt) {
    asm volatile("mbarrier.init.shared.b64 [%0], %1;" :: "r"(addr), "r"(cnt) : "memory");
}
__device__ __forceinline__ void mbar_expect_tx(unsigned addr, unsigned bytes) {
    asm volatile("mbarrier.arrive.expect_tx.shared.b64 _, [%0], %1;"
                 :: "r"(addr), "r"(bytes) : "memory");
}
__device__ __forceinline__ void tma_bulk_g2s(unsigned dst, const void* src,
                                             unsigned bytes, unsigned mbar) {
    asm volatile(
        "cp.async.bulk.shared::cluster.global.mbarrier::complete_tx::bytes "
        "[%0], [%1], %2, [%3];"
        :: "r"(dst), "l"(src), "r"(bytes), "r"(mbar) : "memory");
}
__device__ __forceinline__ void mbar_wait(unsigned addr, int phase) {
    asm volatile(
        "{\n\t.reg .pred P;\n\t"
        "W_%=:\n\t"
        "mbarrier.try_wait.parity.acquire.cta.shared::cta.b64 P, [%0], %1, 0x989680;\n\t"
        "@P bra D_%=;\n\t"
        "bra W_%=;\n\t"
        "D_%=:\n\t}"
        :: "r"(addr), "r"(phase) : "memory");
}

// ---------------------------------------------------------------------------
// Kernel 1: softmax over C=16 for both preds (packed fp32) + zero state.
// ---------------------------------------------------------------------------
__device__ __forceinline__ void softmax16(const float4* __restrict__ src,
                                          float4* __restrict__ dst) {
    float4 a[4];
#pragma unroll
    for (int i = 0; i < 4; i++) a[i] = src[i];
    float* x = reinterpret_cast<float*>(a);
    float m = x[0];
#pragma unroll
    for (int i = 1; i < 16; i++) m = fmaxf(m, x[i]);
    float s = 0.f;
#pragma unroll
    for (int i = 0; i < 16; i++) { float e = expf(x[i] - m); x[i] = e; s += e; }
    float r = 1.0f / s;
#pragma unroll
    for (int i = 0; i < 16; i++) x[i] *= r;
#pragma unroll
    for (int i = 0; i < 4; i++) dst[i] = a[i];
}

__global__ void softmax_kernel(const float* __restrict__ pred_s,
                               const float* __restrict__ pred_t) {
    int v = blockIdx.x * blockDim.x + threadIdx.x;
    int nthr = gridDim.x * blockDim.x;
    for (int i = v; i < E; i += nthr) g_cnt[i] = 0;
    for (int i = v; i < 32 * E; i += nthr) g_Ssum[i] = 0.f;
    if (v == 0) { g_acc[0] = 0.f; g_acc[1] = 0.f; g_not_int01 = 0; g_not_f01 = 0; }
    if (v >= V) return;
    float4* dst = reinterpret_cast<float4*>(g_P + (size_t)v * 32);
    softmax16(reinterpret_cast<const float4*>(pred_s + (size_t)v * 16), dst);
    softmax16(reinterpret_cast<const float4*>(pred_t + (size_t)v * 16), dst + 4);
}

// ---------------------------------------------------------------------------
// Kernel 1b: detect e_mask storage dtype (uint8 vs int32 vs float32).
// ---------------------------------------------------------------------------
__global__ void detect_mask_kernel(const unsigned int* __restrict__ mask_w) {
    int i = blockIdx.x * blockDim.x + threadIdx.x;
    if (i >= E / 4) return;
    unsigned int w = mask_w[i];
    if (w > 1u) atomicOr(&g_not_int01, 1);
    if (w != 0u && w != 0x3f800000u) atomicOr(&g_not_f01, 1);
}

// ---------------------------------------------------------------------------
// Kernel 2 (pass 1): TMA-streamed H scan. 1000 CTAs x 256 thr; each CTA owns
// 50 consecutive H rows. Per row: one 20 KB cp.async.bulk into a
// double-buffered smem pair (mbarrier-paced, next row prefetched while the
// current one is scanned). Scan = LDS.128 + integer OR test; rare hits ->
// spread atomicAdd + list store. No LDG of H anywhere: the stream runs at
// the TMA/LTS rate, decoupled from SM issue.
// ---------------------------------------------------------------------------
__global__ void __launch_bounds__(256) build_kernel(const float* __restrict__ H) {
    __shared__ alignas(128) uint4 sbuf[2][E4];      // 2 x 20000 B
    __shared__ alignas(8) unsigned long long mbar[2];
    const int tid = threadIdx.x;
    const int r0 = blockIdx.x * RPC;

    unsigned mb[2], sb[2];
#pragma unroll
    for (int b = 0; b < 2; b++) {
        mb[b] = smem_u32(&mbar[b]);
        sb[b] = smem_u32(&sbuf[b][0]);
    }
    if (tid == 0) { mbar_init(mb[0], 1); mbar_init(mb[1], 1); }
    __syncthreads();

    int phase[2] = {0, 0};
    if (tid == 0) {                                  // prologue: row r0 -> buf0
        mbar_expect_tx(mb[0], ROWB);
        tma_bulk_g2s(sb[0], H + (size_t)r0 * E, ROWB, mb[0]);
    }

    for (int i = 0; i < RPC; i++) {
        const int buf = i & 1;
        if (tid == 0 && i + 1 < RPC) {               // prefetch next row
            const int nb = (i + 1) & 1;
            mbar_expect_tx(mb[nb], ROWB);
            tma_bulk_g2s(sb[nb], H + (size_t)(r0 + i + 1) * E, ROWB, mb[nb]);
        }
        mbar_wait(mb[buf], phase[buf]);
        phase[buf] ^= 1;

        const int v = r0 + i;
        for (int j = tid; j < E4; j += 256) {
            uint4 w = sbuf[buf][j];
            if ((w.x | w.y) | (w.z | w.w)) {         // ~7.8% taken
                const int eb = 4 * j;
                if (w.x) { int p = atomicAdd(&g_cnt[eb + 0], 1); if (p < CAP) g_list[(size_t)(eb + 0) * CAP + p] = v; }
                if (w.y) { int p = atomicAdd(&g_cnt[eb + 1], 1); if (p < CAP) g_list[(size_t)(eb + 1) * CAP + p] = v; }
                if (w.z) { int p = atomicAdd(&g_cnt[eb + 2], 1); if (p < CAP) g_list[(size_t)(eb + 2) * CAP + p] = v; }
                if (w.w) { int p = atomicAdd(&g_cnt[eb + 3], 1); if (p < CAP) g_list[(size_t)(eb + 3) * CAP + p] = v; }
            }
        }
        __syncthreads();                             // buf fully scanned before reuse
    }
}

// ---------------------------------------------------------------------------
// Kernel 3 (pass 2): gather (R9 form: fp32 P, GPART=4 warps/edge, lane =
// channel). Warp p walks every-4th group of 8 int4-aligned list entries,
// 8 uniform 128B P-row loads per group, 4 rotating FADD chains, one
// atomicAdd per (e,c) to combine partitions.
// ---------------------------------------------------------------------------
__global__ void __launch_bounds__(128) gather_kernel() {
    const int gw   = (blockIdx.x * 128 + threadIdx.x) >> 5;  // global warp id
    const int lane = threadIdx.x & 31;                       // channel
    const int e    = gw >> 2;
    const int part = gw & (GPART - 1);
    if (e >= E) return;
    const int cnt = min(g_cnt[e], CAP);
    const int* __restrict__ lst = g_list + (size_t)e * CAP;
    const float* __restrict__ Pb = g_P + lane;

    float s0 = 0.f, s1 = 0.f, s2 = 0.f, s3 = 0.f;
    const int nfull = cnt >> 3;                              // groups of 8
    for (int g = part; g < nfull; g += GPART) {
        int4 a = *reinterpret_cast<const int4*>(lst + 8 * g);
        int4 b = *reinterpret_cast<const int4*>(lst + 8 * g + 4);
        s0 += Pb[a.x * 32]; s1 += Pb[a.y * 32];
        s2 += Pb[a.z * 32]; s3 += Pb[a.w * 32];
        s0 += Pb[b.x * 32]; s1 += Pb[b.y * 32];
        s2 += Pb[b.z * 32]; s3 += Pb[b.w * 32];
    }
    if (part == 0) {                                         // tail + deg
        for (int i = nfull * 8; i < cnt; i++) s0 += Pb[lst[i] * 32];
        if (lane == 0) g_Sdeg[e] = (float)cnt;
    }
    atomicAdd(&g_Ssum[(size_t)e * 32 + lane], (s0 + s1) + (s2 + s3));
}

// ---------------------------------------------------------------------------
// Kernel 4: per-edge KL from the [e][c] sums; masked mean via atomics.
// ---------------------------------------------------------------------------
__global__ void finalize_kernel(const void* __restrict__ e_mask) {
    int e = blockIdx.x * blockDim.x + threadIdx.x;
    int mode = (g_not_int01 == 0) ? 1 : ((g_not_f01 == 0) ? 2 : 0);
    bool sel = false;
    if (e < E) {
        if (mode == 1)      sel = ((const int*)e_mask)[e] != 0;
        else if (mode == 2) sel = ((const float*)e_mask)[e] != 0.0f;
        else                sel = ((const unsigned char*)e_mask)[e] != 0;
    }
    float kl = 0.f, cnt = 0.f;
    if (sel) {
        cnt = 1.f;
        float inv = 1.0f / (g_Sdeg[e] * TAUF);
#pragma unroll
        for (int c = 0; c < 16; c++) {
            float xs = g_Ssum[(size_t)e * 32 + c]      * inv + EPSF;
            float xt = g_Ssum[(size_t)e * 32 + 16 + c] * inv + EPSF;
            kl += xt * (logf(xt) - logf(xs));
        }
    }
#pragma unroll
    for (int off = 16; off; off >>= 1) {
        kl  += __shfl_down_sync(0xffffffffu, kl,  off);
        cnt += __shfl_down_sync(0xffffffffu, cnt, off);
    }
    if ((threadIdx.x & 31) == 0) {
        atomicAdd(&g_acc[0], kl);
        atomicAdd(&g_acc[1], cnt);
    }
}

__global__ void out_kernel(float* __restrict__ out) {
    out[0] = g_acc[0] / fmaxf(g_acc[1], 1.0f);
}

// ---------------------------------------------------------------------------
extern "C" void kernel_launch(void* const* d_in, const int* in_sizes, int n_in,
                              void* d_out, int out_size) {
    const float* pred_s = (const float*)d_in[0];
    const float* pred_t = (const float*)d_in[1];
    const float* H      = (const float*)d_in[2];
    const void*  e_mask = d_in[3];
    float* out = (float*)d_out;

    softmax_kernel<<<(V + 255) / 256, 256>>>(pred_s, pred_t);
    detect_mask_kernel<<<(E / 4 + 255) / 256, 256>>>((const unsigned int*)e_mask);
    build_kernel<<<NBLD, 256>>>(H);
    gather_kernel<<<(E * GPART * 32 + 127) / 128, 128>>>();
    finalize_kernel<<<(E + 255) / 256, 256>>>(e_mask);
    out_kernel<<<1, 1>>>(out);
}

// round 12
// speedup vs baseline: 1.3500x; 1.3500x over previous
#include <cuda_runtime.h>
#include <math.h>

#define V 50000
#define E 5000
#define E4 (E / 4)            // 1250 uint4 (nibble-bytes) per H row
#define N4 (V * E4)           // 62,500,000 uint4 total
#define CAP 1536              // per-edge list capacity (deg ~ 1001 +- 31)
#define GPART 4               // warps cooperating per edge in gather
#define NJT 10                // j-tiles of 128 (10*128 = 1280 >= 1250)
#define VCH2 512              // v-chunk in list build (98*512 = 50176; tail 336, %8==0)
#define NVC2 98
#define SCAP2 96              // staged hits per lane-chunk (mean 40, 9-sigma margin)
#define CPITCH 97             // smem pitch (96%32==0 would alias banks on flush)
#define TAUF 0.5f
#define EPSF 1e-8f

// Scratch (__device__ globals; allocation-free rule)
__device__ __align__(16) float g_P[(size_t)V * 32];   // packed softmax [v][0..15]=ps,[16..31]=pt
__device__ unsigned char g_B[(size_t)N4];             // nibble per uint4: nonzero map of H (62.5 MB)
__device__ int   g_cnt[E];                            // per-edge nonzero count (= deg_e)
__device__ __align__(16) int g_list[(size_t)E * CAP]; // per-edge vertex lists (unordered)
__device__ float g_Ssum[(size_t)E * 32];              // [e][c] channel sums (atomic-combined)
__device__ float g_Sdeg[E];                           // deg_e (float)
__device__ float g_acc[2];                            // {kl_sum, mask_count}
__device__ int   g_not_int01;                         // mask-dtype detection flags
__device__ int   g_not_f01;

// ---------------------------------------------------------------------------
// Kernel 1: softmax over C=16 for both preds (packed fp32) + zero state.
// ---------------------------------------------------------------------------
__device__ __forceinline__ void softmax16(const float4* __restrict__ src,
                                          float4* __restrict__ dst) {
    float4 a[4];
#pragma unroll
    for (int i = 0; i < 4; i++) a[i] = src[i];
    float* x = reinterpret_cast<float*>(a);
    float m = x[0];
#pragma unroll
    for (int i = 1; i < 16; i++) m = fmaxf(m, x[i]);
    float s = 0.f;
#pragma unroll
    for (int i = 0; i < 16; i++) { float e = expf(x[i] - m); x[i] = e; s += e; }
    float r = 1.0f / s;
#pragma unroll
    for (int i = 0; i < 16; i++) x[i] *= r;
#pragma unroll
    for (int i = 0; i < 4; i++) dst[i] = a[i];
}

__global__ void softmax_kernel(const float* __restrict__ pred_s,
                               const float* __restrict__ pred_t) {
    int v = blockIdx.x * blockDim.x + threadIdx.x;
    int nthr = gridDim.x * blockDim.x;
    for (int i = v; i < E; i += nthr) g_cnt[i] = 0;
    for (int i = v; i < 32 * E; i += nthr) g_Ssum[i] = 0.f;
    if (v == 0) { g_acc[0] = 0.f; g_acc[1] = 0.f; g_not_int01 = 0; g_not_f01 = 0; }
    if (v >= V) return;
    float4* dst = reinterpret_cast<float4*>(g_P + (size_t)v * 32);
    softmax16(reinterpret_cast<const float4*>(pred_s + (size_t)v * 16), dst);
    softmax16(reinterpret_cast<const float4*>(pred_t + (size_t)v * 16), dst + 4);
}

// ---------------------------------------------------------------------------
// Kernel 1b: detect e_mask storage dtype (uint8 vs int32 vs float32).
// ---------------------------------------------------------------------------
__global__ void detect_mask_kernel(const unsigned int* __restrict__ mask_w) {
    int i = blockIdx.x * blockDim.x + threadIdx.x;
    if (i >= E / 4) return;
    unsigned int w = mask_w[i];
    if (w > 1u) atomicOr(&g_not_int01, 1);
    if (w != 0u && w != 0x3f800000u) atomicOr(&g_not_f01, 1);
}

// ---------------------------------------------------------------------------
// Kernel 2a (compress): the 1 GB stream, perfectly branchless.
// Grid-stride over all 62.5M uint4 of H, 4-deep batched; per uint4 compute a
// 4-bit nonzero nibble and store one byte. No branches, no atomics, no smem,
// no syncs -- a pure bandwidth probe + 16x compression (62.5 MB out).
// ---------------------------------------------------------------------------
__global__ void __launch_bounds__(256) compress_kernel(const float* __restrict__ H) {
    const uint4* __restrict__ H4 = reinterpret_cast<const uint4*>(H);
    const int stride = gridDim.x * blockDim.x;           // 524288
    int q = blockIdx.x * blockDim.x + threadIdx.x;

    for (; q + 3 * stride < N4; q += 4 * stride) {
        uint4 a = __ldg(&H4[q]);
        uint4 b = __ldg(&H4[q + stride]);
        uint4 c = __ldg(&H4[q + 2 * stride]);
        uint4 d = __ldg(&H4[q + 3 * stride]);
        unsigned na = (a.x ? 1u : 0u) | (a.y ? 2u : 0u) | (a.z ? 4u : 0u) | (a.w ? 8u : 0u);
        unsigned nb = (b.x ? 1u : 0u) | (b.y ? 2u : 0u) | (b.z ? 4u : 0u) | (b.w ? 8u : 0u);
        unsigned nc = (c.x ? 1u : 0u) | (c.y ? 2u : 0u) | (c.z ? 4u : 0u) | (c.w ? 8u : 0u);
        unsigned nd = (d.x ? 1u : 0u) | (d.y ? 2u : 0u) | (d.z ? 4u : 0u) | (d.w ? 8u : 0u);
        g_B[q]              = (unsigned char)na;
        g_B[q + stride]     = (unsigned char)nb;
        g_B[q + 2 * stride] = (unsigned char)nc;
        g_B[q + 3 * stride] = (unsigned char)nd;
    }
    for (; q < N4; q += stride) {
        uint4 a = __ldg(&H4[q]);
        g_B[q] = (unsigned char)((a.x ? 1u : 0u) | (a.y ? 2u : 0u) |
                                 (a.z ? 4u : 0u) | (a.w ? 8u : 0u));
    }
}

// ---------------------------------------------------------------------------
// Kernel 2b (list build): stream the 62.5 MB nibble array. grid (NJT, NVC2),
// 128 thr; thread owns column j (4 edges). Hits staged per-lane in smem as
// (v<<4)|nibble; flushed once per chunk with one atomicAdd per nonzero
// component. Overflow beyond SCAP2 (9-sigma) falls back to direct atomics.
// ---------------------------------------------------------------------------
__global__ void __launch_bounds__(128) listbuild_kernel() {
    __shared__ unsigned sbuf[128 * CPITCH];              // ~49.7 KB
    const int tid = threadIdx.x;
    const int j = blockIdx.x * 128 + tid;
    const bool jv = (j < E4);
    const int v0 = blockIdx.y * VCH2;
    const int v1 = min(v0 + VCH2, V);                    // length always %8 == 0
    unsigned* __restrict__ my = sbuf + tid * CPITCH;
    int n = 0;

    const unsigned char* __restrict__ Bp = g_B + (size_t)v0 * E4 + (jv ? j : 0);
    for (int v = v0; v < v1; v += 8, Bp += (size_t)8 * E4) {
        unsigned char b[8];
#pragma unroll
        for (int u = 0; u < 8; u++) b[u] = __ldg(Bp + (size_t)u * E4);
#pragma unroll
        for (int u = 0; u < 8; u++) {
            if (jv && b[u]) {                            // ~7.8% taken
                if (n < SCAP2) {
                    my[n++] = ((unsigned)(v + u) << 4) | b[u];
                } else {                                 // astronomically rare
                    const int eb = 4 * j, vv = v + u;
#pragma unroll
                    for (int cc = 0; cc < 4; cc++)
                        if (b[u] & (1u << cc)) {
                            int p = atomicAdd(&g_cnt[eb + cc], 1);
                            if (p < CAP) g_list[(size_t)(eb + cc) * CAP + p] = vv;
                        }
                }
            }
        }
    }

    if (jv && n > 0) {
#pragma unroll
        for (int cc = 0; cc < 4; cc++) {
            int m = 0;
            for (int i = 0; i < n; i++) m += (my[i] >> cc) & 1;
            if (m) {
                const int e = 4 * j + cc;
                int p = atomicAdd(&g_cnt[e], m);
                for (int i = 0; i < n; i++)
                    if ((my[i] >> cc) & 1) {
                        if (p < CAP) g_list[(size_t)e * CAP + p] = my[i] >> 4;
                        p++;
                    }
            }
        }
    }
}

// ---------------------------------------------------------------------------
// Kernel 3: gather (measured-good R9 form). GPART=4 warps/edge, lane=channel;
// every-4th group of 8 int4-aligned list entries, 4 rotating FADD chains,
// one atomicAdd per (e,c).
// ---------------------------------------------------------------------------
__global__ void __launch_bounds__(128) gather_kernel() {
    const int gw   = (blockIdx.x * 128 + threadIdx.x) >> 5;
    const int lane = threadIdx.x & 31;
    const int e    = gw >> 2;
    const int part = gw & (GPART - 1);
    if (e >= E) return;
    const int cnt = min(g_cnt[e], CAP);
    const int* __restrict__ lst = g_list + (size_t)e * CAP;
    const float* __restrict__ Pb = g_P + lane;

    float s0 = 0.f, s1 = 0.f, s2 = 0.f, s3 = 0.f;
    const int nfull = cnt >> 3;
    for (int g = part; g < nfull; g += GPART) {
        int4 a = *reinterpret_cast<const int4*>(lst + 8 * g);
        int4 b = *reinterpret_cast<const int4*>(lst + 8 * g + 4);
        s0 += Pb[a.x * 32]; s1 += Pb[a.y * 32];
        s2 += Pb[a.z * 32]; s3 += Pb[a.w * 32];
        s0 += Pb[b.x * 32]; s1 += Pb[b.y * 32];
        s2 += Pb[b.z * 32]; s3 += Pb[b.w * 32];
    }
    if (part == 0) {
        for (int i = nfull * 8; i < cnt; i++) s0 += Pb[lst[i] * 32];
        if (lane == 0) g_Sdeg[e] = (float)cnt;
    }
    atomicAdd(&g_Ssum[(size_t)e * 32 + lane], (s0 + s1) + (s2 + s3));
}

// ---------------------------------------------------------------------------
// Kernel 4: per-edge KL from the [e][c] sums; masked mean via atomics.
// ---------------------------------------------------------------------------
__global__ void finalize_kernel(const void* __restrict__ e_mask) {
    int e = blockIdx.x * blockDim.x + threadIdx.x;
    int mode = (g_not_int01 == 0) ? 1 : ((g_not_f01 == 0) ? 2 : 0);
    bool sel = false;
    if (e < E) {
        if (mode == 1)      sel = ((const int*)e_mask)[e] != 0;
        else if (mode == 2) sel = ((const float*)e_mask)[e] != 0.0f;
        else                sel = ((const unsigned char*)e_mask)[e] != 0;
    }
    float kl = 0.f, cnt = 0.f;
    if (sel) {
        cnt = 1.f;
        float inv = 1.0f / (g_Sdeg[e] * TAUF);
#pragma unroll
        for (int c = 0; c < 16; c++) {
            float xs = g_Ssum[(size_t)e * 32 + c]      * inv + EPSF;
            float xt = g_Ssum[(size_t)e * 32 + 16 + c] * inv + EPSF;
            kl += xt * (logf(xt) - logf(xs));
        }
    }
#pragma unroll
    for (int off = 16; off; off >>= 1) {
        kl  += __shfl_down_sync(0xffffffffu, kl,  off);
        cnt += __shfl_down_sync(0xffffffffu, cnt, off);
    }
    if ((threadIdx.x & 31) == 0) {
        atomicAdd(&g_acc[0], kl);
        atomicAdd(&g_acc[1], cnt);
    }
}

__global__ void out_kernel(float* __restrict__ out) {
    out[0] = g_acc[0] / fmaxf(g_acc[1], 1.0f);
}

// ---------------------------------------------------------------------------
extern "C" void kernel_launch(void* const* d_in, const int* in_sizes, int n_in,
                              void* d_out, int out_size) {
    const float* pred_s = (const float*)d_in[0];
    const float* pred_t = (const float*)d_in[1];
    const float* H      = (const float*)d_in[2];
    const void*  e_mask = d_in[3];
    float* out = (float*)d_out;

    softmax_kernel<<<(V + 255) / 256, 256>>>(pred_s, pred_t);
    detect_mask_kernel<<<(E / 4 + 255) / 256, 256>>>((const unsigned int*)e_mask);
    compress_kernel<<<2048, 256>>>(H);
    listbuild_kernel<<<dim3(NJT, NVC2), 128>>>();
    gather_kernel<<<(E * GPART * 32 + 127) / 128, 128>>>();
    finalize_kernel<<<(E + 255) / 256, 256>>>(e_mask);
    out_kernel<<<1, 1>>>(out);
}